// round 5
// baseline (speedup 1.0000x reference)
#include <cuda_runtime.h>
#include <cuda_fp16.h>
#include <math.h>

#define N_ROWS_MAX 100000
#define D 64
#define NGH 16
#define NSC 10
#define EPSF 1e-10f
#define FULL 0xFFFFFFFFu

#define RPW 8          // rows per warp
#define WPB 8          // warps per block
#define RPB (RPW*WPB)  // rows per block = 64

typedef unsigned long long ull;

// Scratch — device globals per allocation rules.
__device__ float   g_rs_raw[(size_t)N_ROWS_MAX * D];    // raw row_sum (fp32, self reads)
__device__ __half2 g_rs_h[(size_t)N_ROWS_MAX * 32];     // rs/(||rs||^2+eps) fp16
__device__ float2  g_ss[N_ROWS_MAX];                    // (inv = 1/(sq+eps), selfsim)
__device__ float2  g_W2[128 * 64];                      // [e][d] = (W[d][e], W[d][e]) dup

// Packed f32x2 helpers (Blackwell FFMA2 — only reachable via PTX)
__device__ __forceinline__ ull pk2(float x, float y) {
    ull r; asm("mov.b64 %0, {%1, %2};" : "=l"(r) : "f"(x), "f"(y)); return r;
}
__device__ __forceinline__ float2 upk2(ull v) {
    float2 r; asm("mov.b64 {%0, %1}, %2;" : "=f"(r.x), "=f"(r.y) : "l"(v)); return r;
}
__device__ __forceinline__ void fma2(ull& d, ull a, ull b, ull c) {
    asm("fma.rn.f32x2 %0, %1, %2, %3;" : "=l"(d) : "l"(a), "l"(b), "l"(c));
}

// ---------------------------------------------------------------------------
// Kernel A: per-row scene sums; stores raw fp32 + scaled fp16 + (inv,selfsim);
// also builds the duplicated-pair W table g_W2[e][d] = (W[d][e], W[d][e]).
// ---------------------------------------------------------------------------
__global__ void rowsum_kernel(const float* __restrict__ scene_emb,
                              const int* __restrict__ cate_scene_pad,
                              const float* __restrict__ agg_W,
                              int n_rows) {
    int gtid = blockIdx.x * blockDim.x + threadIdx.x;

    // W dup-transpose: first 8192 threads, one element each. gtid = e*64 + d.
    if (gtid < 128 * 64) {
        int e = gtid >> 6;
        int d = gtid & 63;
        float w = agg_W[d * 128 + e];
        g_W2[gtid] = make_float2(w, w);
    }

    int row = gtid >> 4;
    int sub = gtid & 15;
    if (row >= n_rows) return;
    int lane = threadIdx.x & 31;
    int group_base = lane & 16;

    int myidx = 0;
    if (sub < NSC) myidx = __ldg(cate_scene_pad + (size_t)row * NSC + sub);

    float4 acc = make_float4(0.f, 0.f, 0.f, 0.f);
#pragma unroll
    for (int k = 0; k < NSC; k++) {
        int j = __shfl_sync(FULL, myidx, group_base + k);
        float4 v = ((const float4*)(scene_emb + (size_t)j * D))[sub];
        acc.x += v.x; acc.y += v.y; acc.z += v.z; acc.w += v.w;
    }

    float sq = acc.x * acc.x + acc.y * acc.y + acc.z * acc.z + acc.w * acc.w;
#pragma unroll
    for (int o = 8; o >= 1; o >>= 1)
        sq += __shfl_xor_sync(FULL, sq, o);

    float inv = 1.0f / (sq + EPSF);

    ((float4*)(g_rs_raw + (size_t)row * D))[sub] = acc;

    __half2 h0 = __floats2half2_rn(acc.x * inv, acc.y * inv);
    __half2 h1 = __floats2half2_rn(acc.z * inv, acc.w * inv);
    uint2 u;
    u.x = *reinterpret_cast<unsigned int*>(&h0);
    u.y = *reinterpret_cast<unsigned int*>(&h1);
    ((uint2*)g_rs_h)[(size_t)row * 16 + sub] = u;

    if (sub == 0) g_ss[row] = make_float2(inv, sq * inv * inv);
}

// Butterfly merge: combine two lane-distributed partial sums at xor-offset o.
__device__ __forceinline__ float bmerge(float a, float b, int o, int lane) {
    float x = (lane & o) ? b : a;
    float y = (lane & o) ? a : b;
    y = __shfl_xor_sync(FULL, y, o);
    return x + y;
}

// ---------------------------------------------------------------------------
// Kernel B: one warp owns 8 rows. Attention -> h[e][r] in shared; then a
// packed-FFMA2 register-tiled matvec (rows packed in pairs).
// ---------------------------------------------------------------------------
__global__ void __launch_bounds__(256, 4)
main_kernel(const float* __restrict__ cate_emb,
            const int* __restrict__ c_cate_pad,
            const float* __restrict__ agg_b,
            float* __restrict__ out,
            int n_rows, int v_cates) {
    __shared__ float sH[WPB][128 * RPW];   // [warp][e][r]

    int tid  = threadIdx.x;
    int warp = tid >> 5;
    int lane = tid & 31;

    int rowbase = blockIdx.x * RPB + warp * RPW;
    float* sHw = sH[warp];

    // ---- Phase 1: attention per row ----
#pragma unroll 1
    for (int r = 0; r < RPW; r++) {
        int row = rowbase + r;
        if (row >= n_rows) break;

        int nidx = 0;
        if (lane < NGH) nidx = __ldg(c_cate_pad + (size_t)row * NGH + lane);

        float2 a_raw = *(const float2*)(g_rs_raw + (size_t)row * D + 2 * lane);
        float2 ss = g_ss[row];                  // (inv, selfsim)
        float2 a_hat = make_float2(a_raw.x * ss.x, a_raw.y * ss.x);

        // 16 neighbor dot partials (fp16 gathers)
        float dtp[16];
#pragma unroll
        for (int j = 0; j < 16; j++) {
            int p = __shfl_sync(FULL, nidx, j);
            float2 rv = __half22float2(__ldg(g_rs_h + (size_t)p * 32 + lane));
            dtp[j] = fmaf(rv.x, a_hat.x, rv.y * a_hat.y);
        }

        // Butterfly merge tree: lane L ends with full dot for j = L>>1
#pragma unroll
        for (int i = 0; i < 8; i++) dtp[i] = bmerge(dtp[i], dtp[i + 8], 16, lane);
#pragma unroll
        for (int i = 0; i < 4; i++) dtp[i] = bmerge(dtp[i], dtp[i + 4],  8, lane);
#pragma unroll
        for (int i = 0; i < 2; i++) dtp[i] = bmerge(dtp[i], dtp[i + 2],  4, lane);
        dtp[0] = bmerge(dtp[0], dtp[1], 2, lane);
        dtp[0] += __shfl_xor_sync(FULL, dtp[0], 1);

        // miu_j at lanes 2j, 2j+1
        int jj = lane >> 1;
        int pj = __shfl_sync(FULL, nidx, jj);
        float miu = (pj < v_cates - 1) ? __expf(dtp[0]) : 0.f;

        // denom across distinct j
        float dv = (lane & 1) ? 0.f : miu;
#pragma unroll
        for (int o = 16; o >= 1; o >>= 1)
            dv += __shfl_xor_sync(FULL, dv, o);

        float miu_self = (row < v_cates - 1) ? __expf(ss.y) : 0.f;
        float rden = 1.0f / (dv + miu_self + EPSF);

        // aggregation: self + 16 neighbors, packed FFMA2 accumulator
        ull accv = __ldg((const ull*)(cate_emb + (size_t)row * D + 2 * lane));
        ull msd  = pk2(miu_self, miu_self);
        {
            ull tmp; fma2(tmp, msd, accv, pk2(0.f, 0.f)); accv = tmp;
        }
#pragma unroll
        for (int j = 0; j < 16; j++) {
            float m = __shfl_sync(FULL, miu, 2 * j);
            int   p = __shfl_sync(FULL, nidx, j);
            ull cv = __ldg((const ull*)(cate_emb + (size_t)p * D + 2 * lane));
            fma2(accv, pk2(m, m), cv, accv);
        }
        float2 agg = upk2(accv);

        // h in [e][r] layout
        int e0 = 2 * lane;
        sHw[e0 * RPW + r]             = a_raw.x;
        sHw[(e0 + 1) * RPW + r]       = a_raw.y;
        sHw[(64 + e0) * RPW + r]      = agg.x * rden;
        sHw[(64 + e0 + 1) * RPW + r]  = agg.y * rden;
    }
    __syncwarp();

    // ---- Phase 2: packed matvec. acc[rp] packs rows (2rp, 2rp+1). ----
    ull accA[4], accB[4];
#pragma unroll
    for (int rp = 0; rp < 4; rp++) { accA[rp] = 0ull; accB[rp] = 0ull; }

    const ull* w2 = (const ull*)g_W2;

#pragma unroll 8
    for (int e = 0; e < 128; e++) {
        ull wA = __ldg(w2 + e * 64 + lane);        // (W[d0][e], W[d0][e])
        ull wB = __ldg(w2 + e * 64 + 32 + lane);   // (W[d1][e], W[d1][e])
        // broadcast LDS.128: rows 0-3 then 4-7 at this e, pre-packed pairs
        ulonglong2 h03 = *(const ulonglong2*)(sHw + e * RPW);
        ulonglong2 h47 = *(const ulonglong2*)(sHw + e * RPW + 4);
        fma2(accA[0], wA, h03.x, accA[0]);
        fma2(accA[1], wA, h03.y, accA[1]);
        fma2(accA[2], wA, h47.x, accA[2]);
        fma2(accA[3], wA, h47.y, accA[3]);
        fma2(accB[0], wB, h03.x, accB[0]);
        fma2(accB[1], wB, h03.y, accB[1]);
        fma2(accB[2], wB, h47.x, accB[2]);
        fma2(accB[3], wB, h47.y, accB[3]);
    }

    float b0 = __ldg(agg_b + lane);
    float b1 = __ldg(agg_b + lane + 32);
#pragma unroll
    for (int rp = 0; rp < 4; rp++) {
        float2 vA = upk2(accA[rp]);
        float2 vB = upk2(accB[rp]);
        int r0 = rowbase + 2 * rp;
        if (r0 < n_rows) {
            float x0 = vA.x + b0, x1 = vB.x + b1;
            float* o = out + (size_t)r0 * D;
            o[lane]      = x0 > 0.f ? x0 : expm1f(x0);
            o[32 + lane] = x1 > 0.f ? x1 : expm1f(x1);
        }
        if (r0 + 1 < n_rows) {
            float y0 = vA.y + b0, y1 = vB.y + b1;
            float* o = out + (size_t)(r0 + 1) * D;
            o[lane]      = y0 > 0.f ? y0 : expm1f(y0);
            o[32 + lane] = y1 > 0.f ? y1 : expm1f(y1);
        }
    }
}

// ---------------------------------------------------------------------------
// Inputs (metadata order):
//  0 cids            int32  [N]       (unused by forward)
//  1 cate_emb_w      f32    [Vc, 64]
//  2 scene_emb_w     f32    [Vs, 64]
//  3 cate_scene_pad  int32  [N, 10]
//  4 c_cate_pad      int32  [N, 16]
//  5 agg_W           f32    [64, 128]
//  6 agg_b           f32    [64]
// out: f32 [N, 64]
// ---------------------------------------------------------------------------
extern "C" void kernel_launch(void* const* d_in, const int* in_sizes, int n_in,
                              void* d_out, int out_size) {
    const float* cate_emb       = (const float*)d_in[1];
    const float* scene_emb      = (const float*)d_in[2];
    const int*   cate_scene_pad = (const int*)d_in[3];
    const int*   c_cate_pad     = (const int*)d_in[4];
    const float* agg_W          = (const float*)d_in[5];
    const float* agg_b          = (const float*)d_in[6];
    float* out = (float*)d_out;

    int n_rows  = in_sizes[4] / NGH;   // 100000
    int v_cates = in_sizes[1] / D;     // 100000

    int threadsA = 256;
    int blocksA = (n_rows * 16 + threadsA - 1) / threadsA;
    rowsum_kernel<<<blocksA, threadsA>>>(scene_emb, cate_scene_pad, agg_W, n_rows);

    int blocksB = (n_rows + RPB - 1) / RPB;
    main_kernel<<<blocksB, 256>>>(cate_emb, c_cate_pad, agg_b,
                                  out, n_rows, v_cates);
}

// round 6
// speedup vs baseline: 1.1105x; 1.1105x over previous
#include <cuda_runtime.h>
#include <cuda_fp16.h>
#include <math.h>

#define N_ROWS_MAX 100000
#define D 64
#define NGH 16
#define NSC 10
#define EPSF 1e-10f
#define FULL 0xFFFFFFFFu

#define RPW 8          // rows per warp
#define WPB 8          // warps per block
#define RPB (RPW*WPB)  // rows per block = 64

typedef unsigned long long ull;

// Scratch — device globals per allocation rules.
__device__ float   g_rs_raw[(size_t)N_ROWS_MAX * D];    // raw row_sum (fp32, self reads)
__device__ __half2 g_rs_h[(size_t)N_ROWS_MAX * 32];     // rs/(||rs||^2+eps) fp16
__device__ float2  g_ss[N_ROWS_MAX];                    // (inv = 1/(sq+eps), selfsim)
__device__ float4  g_W4[32 * 64];                       // [c][d] = W[d][4c..4c+3]

// Packed f32x2 helpers (Blackwell FFMA2 — only reachable via PTX)
__device__ __forceinline__ ull pk2(float x, float y) {
    ull r; asm("mov.b64 %0, {%1, %2};" : "=l"(r) : "f"(x), "f"(y)); return r;
}
__device__ __forceinline__ float2 upk2(ull v) {
    float2 r; asm("mov.b64 {%0, %1}, %2;" : "=f"(r.x), "=f"(r.y) : "l"(v)); return r;
}
__device__ __forceinline__ void fma2(ull& d, ull a, ull b, ull c) {
    asm("fma.rn.f32x2 %0, %1, %2, %3;" : "=l"(d) : "l"(a), "l"(b), "l"(c));
}

// ---------------------------------------------------------------------------
// Kernel A: per-row scene sums; stores raw fp32 + scaled fp16 + (inv,selfsim);
// also transposes W into g_W4.
// ---------------------------------------------------------------------------
__global__ void rowsum_kernel(const float* __restrict__ scene_emb,
                              const int* __restrict__ cate_scene_pad,
                              const float* __restrict__ agg_W,
                              int n_rows) {
    int gtid = blockIdx.x * blockDim.x + threadIdx.x;

    // W transpose: first 2048 threads, one float4 each. gtid = c*64 + d.
    if (gtid < 32 * 64) {
        int c = gtid >> 6;
        int d = gtid & 63;
        g_W4[gtid] = ((const float4*)agg_W)[d * 32 + c];
    }

    int row = gtid >> 4;
    int sub = gtid & 15;
    if (row >= n_rows) return;
    int lane = threadIdx.x & 31;
    int group_base = lane & 16;

    int myidx = 0;
    if (sub < NSC) myidx = __ldg(cate_scene_pad + (size_t)row * NSC + sub);

    float4 acc = make_float4(0.f, 0.f, 0.f, 0.f);
#pragma unroll
    for (int k = 0; k < NSC; k++) {
        int j = __shfl_sync(FULL, myidx, group_base + k);
        float4 v = ((const float4*)(scene_emb + (size_t)j * D))[sub];
        acc.x += v.x; acc.y += v.y; acc.z += v.z; acc.w += v.w;
    }

    float sq = acc.x * acc.x + acc.y * acc.y + acc.z * acc.z + acc.w * acc.w;
#pragma unroll
    for (int o = 8; o >= 1; o >>= 1)
        sq += __shfl_xor_sync(FULL, sq, o);

    float inv = 1.0f / (sq + EPSF);

    ((float4*)(g_rs_raw + (size_t)row * D))[sub] = acc;

    __half2 h0 = __floats2half2_rn(acc.x * inv, acc.y * inv);
    __half2 h1 = __floats2half2_rn(acc.z * inv, acc.w * inv);
    uint2 u;
    u.x = *reinterpret_cast<unsigned int*>(&h0);
    u.y = *reinterpret_cast<unsigned int*>(&h1);
    ((uint2*)g_rs_h)[(size_t)row * 16 + sub] = u;

    if (sub == 0) g_ss[row] = make_float2(inv, sq * inv * inv);
}

// Butterfly merge: combine two lane-distributed partial sums at xor-offset o.
__device__ __forceinline__ float bmerge(float a, float b, int o, int lane) {
    float x = (lane & o) ? b : a;
    float y = (lane & o) ? a : b;
    y = __shfl_xor_sync(FULL, y, o);
    return x + y;
}

// ---------------------------------------------------------------------------
// Kernel B: one warp owns 8 rows. Attention -> h[r][e] in shared (conflict-
// free float2 stores); phase 2 packs FFMA2 over e-pairs (free packing from
// LDS.128 of h and LDG.128 of transposed W).
// ---------------------------------------------------------------------------
__global__ void __launch_bounds__(256, 4)
main_kernel(const float* __restrict__ cate_emb,
            const int* __restrict__ c_cate_pad,
            const float* __restrict__ agg_b,
            float* __restrict__ out,
            int n_rows, int v_cates) {
    __shared__ float sH[WPB][RPW * 128];   // [warp][r][e]

    int tid  = threadIdx.x;
    int warp = tid >> 5;
    int lane = tid & 31;

    int rowbase = blockIdx.x * RPB + warp * RPW;
    float* sHw = sH[warp];

    // ---- Phase 1: attention per row ----
#pragma unroll 1
    for (int r = 0; r < RPW; r++) {
        int row = rowbase + r;
        if (row >= n_rows) break;

        int nidx = 0;
        if (lane < NGH) nidx = __ldg(c_cate_pad + (size_t)row * NGH + lane);

        float2 a_raw = *(const float2*)(g_rs_raw + (size_t)row * D + 2 * lane);
        float2 ss = g_ss[row];                  // (inv, selfsim)
        float2 a_hat = make_float2(a_raw.x * ss.x, a_raw.y * ss.x);

        // 16 neighbor dot partials (fp16 gathers, 1 wavefront each)
        float dtp[16];
#pragma unroll
        for (int j = 0; j < 16; j++) {
            int p = __shfl_sync(FULL, nidx, j);
            float2 rv = __half22float2(__ldg(g_rs_h + (size_t)p * 32 + lane));
            dtp[j] = fmaf(rv.x, a_hat.x, rv.y * a_hat.y);
        }

        // Butterfly merge tree: lane L ends with full dot for j = L>>1
#pragma unroll
        for (int i = 0; i < 8; i++) dtp[i] = bmerge(dtp[i], dtp[i + 8], 16, lane);
#pragma unroll
        for (int i = 0; i < 4; i++) dtp[i] = bmerge(dtp[i], dtp[i + 4],  8, lane);
#pragma unroll
        for (int i = 0; i < 2; i++) dtp[i] = bmerge(dtp[i], dtp[i + 2],  4, lane);
        dtp[0] = bmerge(dtp[0], dtp[1], 2, lane);
        dtp[0] += __shfl_xor_sync(FULL, dtp[0], 1);

        // miu_j at lanes 2j, 2j+1
        int jj = lane >> 1;
        int pj = __shfl_sync(FULL, nidx, jj);
        float miu = (pj < v_cates - 1) ? __expf(dtp[0]) : 0.f;

        // denom across distinct j
        float dv = (lane & 1) ? 0.f : miu;
#pragma unroll
        for (int o = 16; o >= 1; o >>= 1)
            dv += __shfl_xor_sync(FULL, dv, o);

        float miu_self = (row < v_cates - 1) ? __expf(ss.y) : 0.f;
        float rden = 1.0f / (dv + miu_self + EPSF);

        // aggregation: self + 16 neighbors, packed FFMA2 accumulator
        ull cself = __ldg((const ull*)(cate_emb + (size_t)row * D + 2 * lane));
        ull accv;
        fma2(accv, pk2(miu_self, miu_self), cself, pk2(0.f, 0.f));
#pragma unroll
        for (int j = 0; j < 16; j++) {
            float m = __shfl_sync(FULL, miu, 2 * j);
            int   p = __shfl_sync(FULL, nidx, j);
            ull cv = __ldg((const ull*)(cate_emb + (size_t)p * D + 2 * lane));
            fma2(accv, pk2(m, m), cv, accv);
        }
        float2 agg = upk2(accv);

        // h in [r][e] layout — conflict-free float2 stores
        float2* hh = (float2*)(sHw + r * 128);
        hh[lane]      = a_raw;                              // exact row_sum
        hh[32 + lane] = make_float2(agg.x * rden, agg.y * rden);
    }
    __syncwarp();

    // ---- Phase 2: e-pair-packed matvec. accA/B[r] = (sum over even e,
    //      sum over odd e) for output dims d0=lane, d1=lane+32. ----
    ull accA[RPW], accB[RPW];
#pragma unroll
    for (int r = 0; r < RPW; r++) { accA[r] = 0ull; accB[r] = 0ull; }

    const ulonglong2* w2 = (const ulonglong2*)g_W4;

#pragma unroll 4
    for (int c = 0; c < 32; c++) {
        ulonglong2 w0 = __ldg(w2 + c * 64 + lane);        // W[d0][4c..4c+3] as 2 pairs
        ulonglong2 w1 = __ldg(w2 + c * 64 + 32 + lane);   // W[d1][4c..4c+3]
#pragma unroll
        for (int r = 0; r < RPW; r++) {
            ulonglong2 h = *(const ulonglong2*)(sHw + r * 128 + 4 * c);  // broadcast
            fma2(accA[r], w0.x, h.x, accA[r]);
            fma2(accA[r], w0.y, h.y, accA[r]);
            fma2(accB[r], w1.x, h.x, accB[r]);
            fma2(accB[r], w1.y, h.y, accB[r]);
        }
    }

    float b0 = __ldg(agg_b + lane);
    float b1 = __ldg(agg_b + lane + 32);
#pragma unroll
    for (int r = 0; r < RPW; r++) {
        int row = rowbase + r;
        if (row < n_rows) {
            float2 vA = upk2(accA[r]);
            float2 vB = upk2(accB[r]);
            float v0 = vA.x + vA.y + b0;
            float v1 = vB.x + vB.y + b1;
            float* o = out + (size_t)row * D;
            o[lane]      = v0 > 0.f ? v0 : expm1f(v0);
            o[32 + lane] = v1 > 0.f ? v1 : expm1f(v1);
        }
    }
}

// ---------------------------------------------------------------------------
// Inputs (metadata order):
//  0 cids            int32  [N]       (unused by forward)
//  1 cate_emb_w      f32    [Vc, 64]
//  2 scene_emb_w     f32    [Vs, 64]
//  3 cate_scene_pad  int32  [N, 10]
//  4 c_cate_pad      int32  [N, 16]
//  5 agg_W           f32    [64, 128]
//  6 agg_b           f32    [64]
// out: f32 [N, 64]
// ---------------------------------------------------------------------------
extern "C" void kernel_launch(void* const* d_in, const int* in_sizes, int n_in,
                              void* d_out, int out_size) {
    const float* cate_emb       = (const float*)d_in[1];
    const float* scene_emb      = (const float*)d_in[2];
    const int*   cate_scene_pad = (const int*)d_in[3];
    const int*   c_cate_pad     = (const int*)d_in[4];
    const float* agg_W          = (const float*)d_in[5];
    const float* agg_b          = (const float*)d_in[6];
    float* out = (float*)d_out;

    int n_rows  = in_sizes[4] / NGH;   // 100000
    int v_cates = in_sizes[1] / D;     // 100000

    int threadsA = 256;
    int blocksA = (n_rows * 16 + threadsA - 1) / threadsA;
    rowsum_kernel<<<blocksA, threadsA>>>(scene_emb, cate_scene_pad, agg_W, n_rows);

    int blocksB = (n_rows + RPB - 1) / RPB;
    main_kernel<<<blocksB, 256>>>(cate_emb, c_cate_pad, agg_b,
                                  out, n_rows, v_cates);
}

// round 7
// speedup vs baseline: 1.2925x; 1.1639x over previous
#include <cuda_runtime.h>
#include <cuda_fp16.h>
#include <math.h>

#define N_ROWS_MAX 100000
#define D 64
#define NGH 16
#define NSC 10
#define EPSF 1e-10f
#define FULL 0xFFFFFFFFu

#define RPW 8          // rows per warp
#define WPB 8          // warps per block
#define RPB (RPW*WPB)  // rows per block = 64

typedef unsigned long long ull;

// Scratch — device globals per allocation rules.
__device__ float   g_rs_raw[(size_t)N_ROWS_MAX * D];    // raw row_sum (fp32)
__device__ __half2 g_rs_h[(size_t)N_ROWS_MAX * 32];     // rs/(||rs||^2+eps) fp16
__device__ float2  g_ss[N_ROWS_MAX];                    // (inv, selfsim)
__device__ float4  g_W4[32 * 64];                       // [c][d] = W[d][4c..4c+3]

// Packed f32x2 helpers (Blackwell FFMA2 — only reachable via PTX)
__device__ __forceinline__ ull pk2(float x, float y) {
    ull r; asm("mov.b64 %0, {%1, %2};" : "=l"(r) : "f"(x), "f"(y)); return r;
}
__device__ __forceinline__ float2 upk2(ull v) {
    float2 r; asm("mov.b64 {%0, %1}, %2;" : "=f"(r.x), "=f"(r.y) : "l"(v)); return r;
}
__device__ __forceinline__ void fma2(ull& d, ull a, ull b, ull c) {
    asm("fma.rn.f32x2 %0, %1, %2, %3;" : "=l"(d) : "l"(a), "l"(b), "l"(c));
}

// ---------------------------------------------------------------------------
// Kernel A: per-row scene sums; stores raw fp32 + scaled fp16 + (inv,selfsim);
// also transposes W into g_W4.
// ---------------------------------------------------------------------------
__global__ void rowsum_kernel(const float* __restrict__ scene_emb,
                              const int* __restrict__ cate_scene_pad,
                              const float* __restrict__ agg_W,
                              int n_rows) {
    int gtid = blockIdx.x * blockDim.x + threadIdx.x;

    // W transpose: first 2048 threads, one float4 each. gtid = c*64 + d.
    if (gtid < 32 * 64) {
        int c = gtid >> 6;
        int d = gtid & 63;
        g_W4[gtid] = ((const float4*)agg_W)[d * 32 + c];
    }

    int row = gtid >> 4;
    int sub = gtid & 15;
    if (row >= n_rows) return;
    int lane = threadIdx.x & 31;
    int group_base = lane & 16;

    int myidx = 0;
    if (sub < NSC) myidx = __ldg(cate_scene_pad + (size_t)row * NSC + sub);

    float4 acc = make_float4(0.f, 0.f, 0.f, 0.f);
#pragma unroll
    for (int k = 0; k < NSC; k++) {
        int j = __shfl_sync(FULL, myidx, group_base + k);
        float4 v = ((const float4*)(scene_emb + (size_t)j * D))[sub];
        acc.x += v.x; acc.y += v.y; acc.z += v.z; acc.w += v.w;
    }

    float sq = acc.x * acc.x + acc.y * acc.y + acc.z * acc.z + acc.w * acc.w;
#pragma unroll
    for (int o = 8; o >= 1; o >>= 1)
        sq += __shfl_xor_sync(FULL, sq, o);

    float inv = 1.0f / (sq + EPSF);

    ((float4*)(g_rs_raw + (size_t)row * D))[sub] = acc;

    __half2 h0 = __floats2half2_rn(acc.x * inv, acc.y * inv);
    __half2 h1 = __floats2half2_rn(acc.z * inv, acc.w * inv);
    uint2 u;
    u.x = *reinterpret_cast<unsigned int*>(&h0);
    u.y = *reinterpret_cast<unsigned int*>(&h1);
    ((uint2*)g_rs_h)[(size_t)row * 16 + sub] = u;

    if (sub == 0) g_ss[row] = make_float2(inv, sq * inv * inv);
}

// Butterfly merge: combine two lane-distributed partial sums at xor-offset o.
__device__ __forceinline__ float bmerge(float a, float b, int o, int lane) {
    float x = (lane & o) ? b : a;
    float y = (lane & o) ? a : b;
    y = __shfl_xor_sync(FULL, y, o);
    return x + y;
}

// ---------------------------------------------------------------------------
// Kernel B: one warp owns 8 rows, processed as 4 half-warp row-pairs in
// phase 1 (16 lanes/row, float4/lane). Phase 2: e-pair FFMA2 matvec.
// ---------------------------------------------------------------------------
__global__ void __launch_bounds__(256, 4)
main_kernel(const float* __restrict__ cate_emb,
            const int* __restrict__ c_cate_pad,
            const float* __restrict__ agg_b,
            float* __restrict__ out,
            int n_rows, int v_cates) {
    __shared__ float sH[WPB][RPW * 128];   // [warp][r][e]

    int tid  = threadIdx.x;
    int warp = tid >> 5;
    int lane = tid & 31;

    int rowbase = blockIdx.x * RPB + warp * RPW;
    float* sHw = sH[warp];

    int half = lane >> 4;     // which row of the pair this lane serves
    int sub  = lane & 15;     // 0..15 within half-warp
    int base = lane & 16;     // shuffle base for this half

    // ---- Phase 1: attention, 2 rows per iteration ----
#pragma unroll 1
    for (int rp = 0; rp < RPW / 2; rp++) {
        int row  = rowbase + 2 * rp + half;
        int vrow = row < n_rows ? row : n_rows - 1;   // clamp tail (stores guarded later)

        // each lane owns one neighbor of its row
        int nidx = __ldg(c_cate_pad + (size_t)vrow * NGH + sub);

        float4 a_raw = __ldg((const float4*)(g_rs_raw + (size_t)vrow * D) + sub);
        float2 ss = g_ss[vrow];                       // (inv, selfsim)
        float4 ah = make_float4(a_raw.x * ss.x, a_raw.y * ss.x,
                                a_raw.z * ss.x, a_raw.w * ss.x);

        // 16 neighbor dot partials (fp16 gathers: 16 lanes x 8B = one 128B row)
        float dtp[16];
#pragma unroll
        for (int j = 0; j < 16; j++) {
            int p = __shfl_sync(FULL, nidx, base + j);
            uint2 u = __ldg((const uint2*)g_rs_h + (size_t)p * 16 + sub);
            float2 f0 = __half22float2(*reinterpret_cast<__half2*>(&u.x));
            float2 f1 = __half22float2(*reinterpret_cast<__half2*>(&u.y));
            dtp[j] = fmaf(f0.x, ah.x, fmaf(f0.y, ah.y,
                      fmaf(f1.x, ah.z, f1.y * ah.w)));
        }

        // 16-lane butterfly: lane (base+l) ends holding full dot_l of its row
#pragma unroll
        for (int i = 0; i < 8; i++) dtp[i] = bmerge(dtp[i], dtp[i + 8], 8, lane);
#pragma unroll
        for (int i = 0; i < 4; i++) dtp[i] = bmerge(dtp[i], dtp[i + 4], 4, lane);
#pragma unroll
        for (int i = 0; i < 2; i++) dtp[i] = bmerge(dtp[i], dtp[i + 2], 2, lane);
        dtp[0] = bmerge(dtp[0], dtp[1], 1, lane);

        // lane already owns nidx for its own dot -> local mask, no broadcast
        float miu = (nidx < v_cates - 1) ? __expf(dtp[0]) : 0.f;

        // denom over the 16 lanes of this half
        float dv = miu;
#pragma unroll
        for (int o = 8; o >= 1; o >>= 1)
            dv += __shfl_xor_sync(FULL, dv, o);

        float miu_self = (vrow < v_cates - 1) ? __expf(ss.y) : 0.f;
        float rden = 1.0f / (dv + miu_self + EPSF);

        // aggregation: self + 16 neighbors, packed FFMA2, float4 lanes
        ulonglong2 cs = __ldg((const ulonglong2*)(cate_emb + (size_t)vrow * D) + sub);
        ull msd = pk2(miu_self, miu_self);
        ull acc01, acc23;
        fma2(acc01, msd, cs.x, pk2(0.f, 0.f));
        fma2(acc23, msd, cs.y, pk2(0.f, 0.f));
#pragma unroll
        for (int j = 0; j < 16; j++) {
            float m = __shfl_sync(FULL, miu, base + j);
            int   p = __shfl_sync(FULL, nidx, base + j);
            ulonglong2 cv = __ldg((const ulonglong2*)(cate_emb + (size_t)p * D) + sub);
            ull mm = pk2(m, m);
            fma2(acc01, mm, cv.x, acc01);
            fma2(acc23, mm, cv.y, acc23);
        }
        float2 g01 = upk2(acc01);
        float2 g23 = upk2(acc23);

        // h in [r][e] layout — float4 stores, conflict-free
        float* hrow = sHw + (2 * rp + half) * 128;
        ((float4*)hrow)[sub]      = a_raw;                      // exact row_sum
        ((float4*)hrow)[16 + sub] = make_float4(g01.x * rden, g01.y * rden,
                                                g23.x * rden, g23.y * rden);
    }
    __syncwarp();

    // ---- Phase 2: e-pair-packed matvec (unchanged) ----
    ull accA[RPW], accB[RPW];
#pragma unroll
    for (int r = 0; r < RPW; r++) { accA[r] = 0ull; accB[r] = 0ull; }

    const ulonglong2* w2 = (const ulonglong2*)g_W4;

#pragma unroll 4
    for (int c = 0; c < 32; c++) {
        ulonglong2 w0 = __ldg(w2 + c * 64 + lane);        // W[d0][4c..4c+3]
        ulonglong2 w1 = __ldg(w2 + c * 64 + 32 + lane);   // W[d1][4c..4c+3]
#pragma unroll
        for (int r = 0; r < RPW; r++) {
            ulonglong2 h = *(const ulonglong2*)(sHw + r * 128 + 4 * c);  // broadcast
            fma2(accA[r], w0.x, h.x, accA[r]);
            fma2(accA[r], w0.y, h.y, accA[r]);
            fma2(accB[r], w1.x, h.x, accB[r]);
            fma2(accB[r], w1.y, h.y, accB[r]);
        }
    }

    float b0 = __ldg(agg_b + lane);
    float b1 = __ldg(agg_b + lane + 32);
#pragma unroll
    for (int r = 0; r < RPW; r++) {
        int row = rowbase + r;
        if (row < n_rows) {
            float2 vA = upk2(accA[r]);
            float2 vB = upk2(accB[r]);
            float v0 = vA.x + vA.y + b0;
            float v1 = vB.x + vB.y + b1;
            float* o = out + (size_t)row * D;
            o[lane]      = v0 > 0.f ? v0 : expm1f(v0);
            o[32 + lane] = v1 > 0.f ? v1 : expm1f(v1);
        }
    }
}

// ---------------------------------------------------------------------------
// Inputs (metadata order):
//  0 cids            int32  [N]       (unused by forward)
//  1 cate_emb_w      f32    [Vc, 64]
//  2 scene_emb_w     f32    [Vs, 64]
//  3 cate_scene_pad  int32  [N, 10]
//  4 c_cate_pad      int32  [N, 16]
//  5 agg_W           f32    [64, 128]
//  6 agg_b           f32    [64]
// out: f32 [N, 64]
// ---------------------------------------------------------------------------
extern "C" void kernel_launch(void* const* d_in, const int* in_sizes, int n_in,
                              void* d_out, int out_size) {
    const float* cate_emb       = (const float*)d_in[1];
    const float* scene_emb      = (const float*)d_in[2];
    const int*   cate_scene_pad = (const int*)d_in[3];
    const int*   c_cate_pad     = (const int*)d_in[4];
    const float* agg_W          = (const float*)d_in[5];
    const float* agg_b          = (const float*)d_in[6];
    float* out = (float*)d_out;

    int n_rows  = in_sizes[4] / NGH;   // 100000
    int v_cates = in_sizes[1] / D;     // 100000

    int threadsA = 256;
    int blocksA = (n_rows * 16 + threadsA - 1) / threadsA;
    rowsum_kernel<<<blocksA, threadsA>>>(scene_emb, cate_scene_pad, agg_W, n_rows);

    int blocksB = (n_rows + RPB - 1) / RPB;
    main_kernel<<<blocksB, 256>>>(cate_emb, c_cate_pad, agg_b,
                                  out, n_rows, v_cates);
}